// round 16
// baseline (speedup 1.0000x reference)
#include <cuda_runtime.h>
#include <cuda_fp16.h>
#include <cuda_bf16.h>

#define NN 50000
#define EE 800000
#define F1 128
#define F2 256   // HEADS*HID
#define HEADS 16
#define HID 16
#define OUTC 64
#define NEG_SLOPE 0.2f
#define EPSV 1e-16f
#define SCAN_BLK 49

// ---------------- scratch (zero-initialized at module load) --------------------
__device__ __half g_xh[(size_t)NN * F1];     // x in half
__device__ __half g_w1t[F2 * F1];            // W1^T [n][k], swizzled, half
__device__ __half g_w2t[OUTC * F2];          // W2^T [n][k], swizzled, half
__device__ __half g_h1h[(size_t)NN * F2];
__device__ __half g_out1h[(size_t)NN * F2];
__device__ __half g_h2h[(size_t)NN * OUTC];
__device__ float  g_as1[(size_t)NN * HEADS];
__device__ float  g_ad1[(size_t)NN * HEADS];
__device__ float  g_as2[NN];
__device__ float  g_ad2[NN];
__device__ int    g_cnt[NN];
__device__ int    g_off[NN + 1];
__device__ int    g_esrc[EE];
__device__ int    g_rank[EE];
__device__ int    g_bsum[64];

// ---------------- helpers -----------------------------------------------------
__device__ __forceinline__ float lrelu(float e) { return e > 0.f ? e : NEG_SLOPE * e; }

__device__ __forceinline__ int is_i32(const void* ei) {
    const int* w = (const int*)ei;
    return (w[1] | w[3] | w[5] | w[7]) != 0;
}

__device__ __forceinline__ void hmma16816(float* d, const unsigned* a, const unsigned* b) {
    asm volatile(
        "mma.sync.aligned.m16n8k16.row.col.f32.f16.f16.f32 "
        "{%0,%1,%2,%3}, {%4,%5,%6,%7}, {%8,%9}, {%0,%1,%2,%3};"
        : "+f"(d[0]), "+f"(d[1]), "+f"(d[2]), "+f"(d[3])
        : "r"(a[0]), "r"(a[1]), "r"(a[2]), "r"(a[3]), "r"(b[0]), "r"(b[1]));
}

__device__ __forceinline__ void ldsm_x4(unsigned& r0, unsigned& r1, unsigned& r2,
                                        unsigned& r3, unsigned addr) {
    asm volatile("ldmatrix.sync.aligned.m8n8.x4.shared.b16 {%0,%1,%2,%3}, [%4];"
                 : "=r"(r0), "=r"(r1), "=r"(r2), "=r"(r3) : "r"(addr));
}

__device__ __forceinline__ void cp16(unsigned dst, const void* src, int sz) {
    asm volatile("cp.async.cg.shared.global [%0], [%1], 16, %2;"
                 :: "r"(dst), "l"(src), "r"(sz));
}

// ---------------- converts --------------------------------------------------------
__global__ void xconv_kernel(const float* __restrict__ x) {
    int i = blockIdx.x * blockDim.x + threadIdx.x;
    if (i >= NN * F1 / 4) return;
    float4 v = ((const float4*)x)[i];
    __half2 p0 = __floats2half2_rn(v.x, v.y);
    __half2 p1 = __floats2half2_rn(v.z, v.w);
    uint2 u; u.x = *(unsigned*)&p0; u.y = *(unsigned*)&p1;
    ((uint2*)g_xh)[i] = u;
}

// W1^T and W2^T with LDSM XOR swizzle baked into global layout
__global__ void wt_kernel(const float* __restrict__ W1, const float* __restrict__ W2) {
    int idx = blockIdx.x * blockDim.x + threadIdx.x;
    if (idx < F1 * F2) {                      // W1: [k=128][n=256]
        int k = idx >> 8, n = idx & 255;
        int sw = ((n >> 3) & 7) << 3;
        int ks = (k & 64) | ((k & 63) ^ sw);
        g_w1t[n * F1 + ks] = __float2half_rn(W1[idx]);
    } else if (idx < F1 * F2 + F2 * OUTC) {   // W2: [k=256][n=64]
        int j = idx - F1 * F2;
        int k = j >> 6, n = j & 63;
        int sw = ((n >> 3) & 7) << 3;
        int ks = (k & 192) | ((k & 63) ^ sw);
        g_w2t[n * F2 + ks] = __float2half_rn(W2[j]);
    }
}

// ---------------- hist (+rank), 8 edges/thread --------------------------------------
__global__ void hist_kernel(const void* ei) {
    int i = (blockIdx.x * blockDim.x + threadIdx.x) * 8;
    if (i >= EE) return;
    int d[8];
    if (is_i32(ei)) {
        const int* p = (const int*)ei;
        int4 a = *(const int4*)&p[EE + i];
        int4 b = *(const int4*)&p[EE + i + 4];
        d[0] = a.x; d[1] = a.y; d[2] = a.z; d[3] = a.w;
        d[4] = b.x; d[5] = b.y; d[6] = b.z; d[7] = b.w;
    } else {
        const long long* p = (const long long*)ei;
#pragma unroll
        for (int j = 0; j < 4; j++) {
            longlong2 v = *(const longlong2*)&p[EE + i + j * 2];
            d[j * 2] = (int)v.x; d[j * 2 + 1] = (int)v.y;
        }
    }
    int r[8];
#pragma unroll
    for (int j = 0; j < 8; j++) r[j] = atomicAdd(&g_cnt[d[j]], 1);
#pragma unroll
    for (int j = 0; j < 8; j++) g_rank[i + j] = r[j];
}

// ---------------- two-phase scan ------------------------------------------------------
__global__ void scanA_kernel() {
    __shared__ int wsum[32];
    int i = blockIdx.x * 1024 + threadIdx.x;
    int lane = threadIdx.x & 31, wid = threadIdx.x >> 5;
    int x = (i < NN) ? g_cnt[i] : 0;
    int incl = x;
#pragma unroll
    for (int d = 1; d < 32; d <<= 1) {
        int t = __shfl_up_sync(0xffffffffu, incl, d);
        if (lane >= d) incl += t;
    }
    if (lane == 31) wsum[wid] = incl;
    __syncthreads();
    if (wid == 0) {
        int y = wsum[lane];
#pragma unroll
        for (int d = 1; d < 32; d <<= 1) {
            int t = __shfl_up_sync(0xffffffffu, y, d);
            if (lane >= d) y += t;
        }
        wsum[lane] = y;
    }
    __syncthreads();
    if (wid > 0) incl += wsum[wid - 1];
    if (i < NN) g_off[i + 1] = incl;
    if (threadIdx.x == 1023) g_bsum[blockIdx.x] = incl;
}

__global__ void scanC_kernel() {
    __shared__ int sb[64];
    __shared__ int base_s;
    int t = threadIdx.x;
    if (t < 64) sb[t] = (t < SCAN_BLK) ? g_bsum[t] : 0;
    __syncthreads();
    if (t == 0) {
        int s = 0;
        int n = blockIdx.x;
        for (int j = 0; j < n; j++) s += sb[j];
        base_s = s;
    }
    __syncthreads();
    int i = blockIdx.x * 1024 + t;
    if (i < NN) {
        g_off[i + 1] += base_s;
        g_cnt[i] = 0;
    }
    if (i == 0) g_off[0] = 0;
}

// ---------------- scatter without atomics, 8 edges/thread ----------------------------
__global__ void scatter_kernel(const void* ei) {
    int i = (blockIdx.x * blockDim.x + threadIdx.x) * 8;
    if (i >= EE) return;
    int s[8], d[8];
    if (is_i32(ei)) {
        const int* p = (const int*)ei;
        int4 sa = *(const int4*)&p[i];
        int4 sbv = *(const int4*)&p[i + 4];
        int4 da = *(const int4*)&p[EE + i];
        int4 db = *(const int4*)&p[EE + i + 4];
        s[0] = sa.x; s[1] = sa.y; s[2] = sa.z; s[3] = sa.w;
        s[4] = sbv.x; s[5] = sbv.y; s[6] = sbv.z; s[7] = sbv.w;
        d[0] = da.x; d[1] = da.y; d[2] = da.z; d[3] = da.w;
        d[4] = db.x; d[5] = db.y; d[6] = db.z; d[7] = db.w;
    } else {
        const long long* p = (const long long*)ei;
#pragma unroll
        for (int j = 0; j < 4; j++) {
            longlong2 sv = *(const longlong2*)&p[i + j * 2];
            longlong2 dv = *(const longlong2*)&p[EE + i + j * 2];
            s[j * 2] = (int)sv.x; s[j * 2 + 1] = (int)sv.y;
            d[j * 2] = (int)dv.x; d[j * 2 + 1] = (int)dv.y;
        }
    }
    int4 ra = *(const int4*)&g_rank[i];
    int4 rb = *(const int4*)&g_rank[i + 4];
    int r[8] = {ra.x, ra.y, ra.z, ra.w, rb.x, rb.y, rb.z, rb.w};
    int o[8];
#pragma unroll
    for (int j = 0; j < 8; j++) o[j] = g_off[d[j]];
#pragma unroll
    for (int j = 0; j < 8; j++) g_esrc[o[j] + r[j]] = s[j];
}

// ---------------- GEMM1: cp.async full-K single stage, fused 16-head alpha -------
__global__ void gemm1_ca(const __half* __restrict__ Axh, const __half* __restrict__ w1t,
                         __half* __restrict__ C,
                         const float* __restrict__ avs, const float* __restrict__ avd,
                         float* __restrict__ as_out, float* __restrict__ ad_out, int M) {
    extern __shared__ __half sm[];
    __half* As = sm;                 // [128][136]
    __half* Bs = sm + 128 * 136;     // [64][136]

    int tid = threadIdx.x;
    int wid = tid >> 5, lane = tid & 31;
    int wm = wid & 3, wn = wid >> 2;
    int row0 = blockIdx.y * 128, col0 = blockIdx.x * 64;
    int lr = lane >> 2, lc = lane & 3;

    unsigned as_base = (unsigned)__cvta_generic_to_shared(As);
    unsigned bs_base = (unsigned)__cvta_generic_to_shared(Bs);

    int g8 = lane >> 3, ri = lane & 7;
    int gA_row = ((g8 & 1) << 3) + ri;
    int gA_col = (g8 >> 1) << 3;
    int gB_nhi = (g8 >> 1) << 3;
    int gB_k   = (g8 & 1) << 3;

#pragma unroll
    for (int l = 0; l < 8; l++) {
        int idx = tid + l * 256;
        int r = idx >> 4, c = idx & 15;
        int gr = row0 + r;
        unsigned dst = as_base + (unsigned)((r * 136 + c * 8) * 2);
        const __half* src = &Axh[(size_t)gr * F1 + c * 8];
        cp16(dst, src, (gr < M) ? 16 : 0);
    }
#pragma unroll
    for (int l = 0; l < 4; l++) {
        int idx = tid + l * 256;
        int r = idx >> 4, c = idx & 15;
        unsigned dst = bs_base + (unsigned)((r * 136 + c * 8) * 2);
        const __half* src = &w1t[(size_t)(col0 + r) * F1 + c * 8];
        cp16(dst, src, 16);
    }
    asm volatile("cp.async.commit_group;");
    asm volatile("cp.async.wait_group 0;");
    __syncthreads();

    float d[2][4][4];
#pragma unroll
    for (int a = 0; a < 2; a++)
#pragma unroll
        for (int b = 0; b < 4; b++)
#pragma unroll
            for (int c = 0; c < 4; c++) d[a][b][c] = 0.f;

#pragma unroll
    for (int kk = 0; kk < 8; kk++) {
        int kb = kk * 16;
        unsigned afr[2][4], bfr[4][2];
#pragma unroll
        for (int mt = 0; mt < 2; mt++) {
            int r = wm * 32 + mt * 16 + gA_row;
            unsigned addr = as_base + (unsigned)((r * 136 + kb + gA_col) * 2);
            ldsm_x4(afr[mt][0], afr[mt][1], afr[mt][2], afr[mt][3], addr);
        }
#pragma unroll
        for (int ntp = 0; ntp < 2; ntp++) {
            int nrow = wn * 32 + ntp * 16 + gB_nhi + ri;
            int sw = ((nrow >> 3) & 7) << 3;
            int kidx = (kb + gB_k) ^ sw;
            unsigned addr = bs_base + (unsigned)((nrow * 136 + kidx) * 2);
            ldsm_x4(bfr[ntp * 2][0], bfr[ntp * 2][1],
                    bfr[ntp * 2 + 1][0], bfr[ntp * 2 + 1][1], addr);
        }
#pragma unroll
        for (int mt = 0; mt < 2; mt++)
#pragma unroll
            for (int nt = 0; nt < 4; nt++)
                hmma16816(d[mt][nt], afr[mt], bfr[nt]);
    }

#pragma unroll
    for (int mt = 0; mt < 2; mt++) {
        int gr0 = row0 + wm * 32 + mt * 16 + lr;
#pragma unroll
        for (int nt = 0; nt < 4; nt++) {
            int gc = col0 + wn * 32 + nt * 8 + lc * 2;
            if (gr0 < M) {
                __half2 p = __floats2half2_rn(d[mt][nt][0], d[mt][nt][1]);
                *(unsigned*)&C[(size_t)gr0 * F2 + gc] = *(unsigned*)&p;
            }
            if (gr0 + 8 < M) {
                __half2 p = __floats2half2_rn(d[mt][nt][2], d[mt][nt][3]);
                *(unsigned*)&C[(size_t)(gr0 + 8) * F2 + gc] = *(unsigned*)&p;
            }
        }
    }

#pragma unroll
    for (int mt = 0; mt < 2; mt++) {
#pragma unroll
        for (int hp = 0; hp < 2; hp++) {
            int h = blockIdx.x * 4 + wn * 2 + hp;
            float psr = 0.f, pdr = 0.f, psr8 = 0.f, pdr8 = 0.f;
#pragma unroll
            for (int half_t = 0; half_t < 2; half_t++) {
                int nt = hp * 2 + half_t;
                int cl = half_t * 8 + lc * 2;
                float w0s = avs[h * HID + cl], w1s = avs[h * HID + cl + 1];
                float w0d = avd[h * HID + cl], w1d = avd[h * HID + cl + 1];
                psr  += d[mt][nt][0] * w0s + d[mt][nt][1] * w1s;
                pdr  += d[mt][nt][0] * w0d + d[mt][nt][1] * w1d;
                psr8 += d[mt][nt][2] * w0s + d[mt][nt][3] * w1s;
                pdr8 += d[mt][nt][2] * w0d + d[mt][nt][3] * w1d;
            }
#pragma unroll
            for (int dx = 1; dx <= 2; dx <<= 1) {
                psr  += __shfl_xor_sync(0xffffffffu, psr, dx);
                pdr  += __shfl_xor_sync(0xffffffffu, pdr, dx);
                psr8 += __shfl_xor_sync(0xffffffffu, psr8, dx);
                pdr8 += __shfl_xor_sync(0xffffffffu, pdr8, dx);
            }
            if (lc == 0) {
                int gr = row0 + wm * 32 + mt * 16 + lr;
                if (gr < M) {
                    as_out[(size_t)gr * HEADS + h] = psr;
                    ad_out[(size_t)gr * HEADS + h] = pdr;
                }
                if (gr + 8 < M) {
                    as_out[(size_t)(gr + 8) * HEADS + h] = psr8;
                    ad_out[(size_t)(gr + 8) * HEADS + h] = pdr8;
                }
            }
        }
    }
}

// ---------------- GEMM2: cp.async pipelined (B resident, A double-buffered) ------
__global__ void gemm2_ca(const __half* __restrict__ A, const __half* __restrict__ w2t,
                         __half* __restrict__ C,
                         const float* __restrict__ avs, const float* __restrict__ avd,
                         float* __restrict__ as_out, float* __restrict__ ad_out, int M) {
    extern __shared__ __half sm[];
    __half* As = sm;                     // 2 stages x [128][72]
    __half* Bs = sm + 2 * 128 * 72;      // [64][264]
    __shared__ float sAs[128], sAd[128];

    int tid = threadIdx.x;
    int wid = tid >> 5, lane = tid & 31;
    int wm = wid & 3, wn = wid >> 2;
    int row0 = blockIdx.x * 128;
    int lr = lane >> 2, lc = lane & 3;

    unsigned as_base = (unsigned)__cvta_generic_to_shared(As);
    unsigned bs_base = (unsigned)__cvta_generic_to_shared(Bs);

    int g8 = lane >> 3, ri = lane & 7;
    int gA_row = ((g8 & 1) << 3) + ri;
    int gA_col = (g8 >> 1) << 3;
    int gB_nhi = (g8 >> 1) << 3;
    int gB_k   = (g8 & 1) << 3;

    // issue B (64 rows x 32 chunks = 2048 / 256 thr = 8 each) + A chunk 0 -> G0
#pragma unroll
    for (int l = 0; l < 8; l++) {
        int idx = tid + l * 256;
        int r = idx >> 5, c = idx & 31;
        unsigned dst = bs_base + (unsigned)((r * 264 + c * 8) * 2);
        cp16(dst, &w2t[(size_t)r * F2 + c * 8], 16);
    }
    {
        // A chunk 0 into stage 0: 128 rows x 8 chunks = 1024 / 256 = 4 each
#pragma unroll
        for (int l = 0; l < 4; l++) {
            int idx = tid + l * 256;
            int r = idx >> 3, c = idx & 7;
            int gr = row0 + r;
            unsigned dst = as_base + (unsigned)((r * 72 + c * 8) * 2);
            cp16(dst, &A[(size_t)gr * F2 + 0 + c * 8], (gr < M) ? 16 : 0);
        }
    }
    asm volatile("cp.async.commit_group;");
    {
        // A chunk 1 into stage 1 -> G1
#pragma unroll
        for (int l = 0; l < 4; l++) {
            int idx = tid + l * 256;
            int r = idx >> 3, c = idx & 7;
            int gr = row0 + r;
            unsigned dst = as_base + (unsigned)((128 * 72 + r * 72 + c * 8) * 2);
            cp16(dst, &A[(size_t)gr * F2 + 64 + c * 8], (gr < M) ? 16 : 0);
        }
    }
    asm volatile("cp.async.commit_group;");

    float d[2][4][4];
#pragma unroll
    for (int a = 0; a < 2; a++)
#pragma unroll
        for (int b = 0; b < 4; b++)
#pragma unroll
            for (int c = 0; c < 4; c++) d[a][b][c] = 0.f;

#pragma unroll
    for (int kc = 0; kc < 4; kc++) {
        if (kc < 3) asm volatile("cp.async.wait_group 1;");
        else        asm volatile("cp.async.wait_group 0;");
        __syncthreads();

        unsigned stage = as_base + (unsigned)((kc & 1) * 128 * 72 * 2);
#pragma unroll
        for (int kk = 0; kk < 4; kk++) {
            int kbl = kk * 16;                 // local k within chunk
            int kbg = kc * 64 + kbl;           // global k for B
            unsigned afr[2][4], bfr[4][2];
#pragma unroll
            for (int mt = 0; mt < 2; mt++) {
                int r = wm * 32 + mt * 16 + gA_row;
                unsigned addr = stage + (unsigned)((r * 72 + kbl + gA_col) * 2);
                ldsm_x4(afr[mt][0], afr[mt][1], afr[mt][2], afr[mt][3], addr);
            }
#pragma unroll
            for (int ntp = 0; ntp < 2; ntp++) {
                int nrow = wn * 32 + ntp * 16 + gB_nhi + ri;
                int sw = ((nrow >> 3) & 7) << 3;
                int kidx = (kbg + gB_k) ^ sw;   // XOR touches only low-6 bits
                unsigned addr = bs_base + (unsigned)((nrow * 264 + kidx) * 2);
                ldsm_x4(bfr[ntp * 2][0], bfr[ntp * 2][1],
                        bfr[ntp * 2 + 1][0], bfr[ntp * 2 + 1][1], addr);
            }
#pragma unroll
            for (int mt = 0; mt < 2; mt++)
#pragma unroll
                for (int nt = 0; nt < 4; nt++)
                    hmma16816(d[mt][nt], afr[mt], bfr[nt]);
        }
        __syncthreads();

        if (kc + 2 < 4) {
            // issue A chunk kc+2 into stage kc&1
#pragma unroll
            for (int l = 0; l < 4; l++) {
                int idx = tid + l * 256;
                int r = idx >> 3, c = idx & 7;
                int gr = row0 + r;
                unsigned dst = as_base + (unsigned)(((kc & 1) * 128 * 72 + r * 72 + c * 8) * 2);
                cp16(dst, &A[(size_t)gr * F2 + (kc + 2) * 64 + c * 8], (gr < M) ? 16 : 0);
            }
            asm volatile("cp.async.commit_group;");
        }
    }

#pragma unroll
    for (int mt = 0; mt < 2; mt++) {
        int gr0 = row0 + wm * 32 + mt * 16 + lr;
#pragma unroll
        for (int nt = 0; nt < 4; nt++) {
            int gc = wn * 32 + nt * 8 + lc * 2;
            if (gr0 < M) {
                __half2 p = __floats2half2_rn(d[mt][nt][0], d[mt][nt][1]);
                *(unsigned*)&C[(size_t)gr0 * OUTC + gc] = *(unsigned*)&p;
            }
            if (gr0 + 8 < M) {
                __half2 p = __floats2half2_rn(d[mt][nt][2], d[mt][nt][3]);
                *(unsigned*)&C[(size_t)(gr0 + 8) * OUTC + gc] = *(unsigned*)&p;
            }
        }
    }

#pragma unroll
    for (int mt = 0; mt < 2; mt++) {
        float psr = 0.f, pdr = 0.f, psr8 = 0.f, pdr8 = 0.f;
#pragma unroll
        for (int nt = 0; nt < 4; nt++) {
            int cl = wn * 32 + nt * 8 + lc * 2;
            float w0s = avs[cl], w1s = avs[cl + 1];
            float w0d = avd[cl], w1d = avd[cl + 1];
            psr  += d[mt][nt][0] * w0s + d[mt][nt][1] * w1s;
            pdr  += d[mt][nt][0] * w0d + d[mt][nt][1] * w1d;
            psr8 += d[mt][nt][2] * w0s + d[mt][nt][3] * w1s;
            pdr8 += d[mt][nt][2] * w0d + d[mt][nt][3] * w1d;
        }
#pragma unroll
        for (int dx = 1; dx <= 2; dx <<= 1) {
            psr  += __shfl_xor_sync(0xffffffffu, psr, dx);
            pdr  += __shfl_xor_sync(0xffffffffu, pdr, dx);
            psr8 += __shfl_xor_sync(0xffffffffu, psr8, dx);
            pdr8 += __shfl_xor_sync(0xffffffffu, pdr8, dx);
        }
        if (lc == 0 && wn == 0) {
            int lrow = wm * 32 + mt * 16 + lr;
            sAs[lrow] = psr;  sAd[lrow] = pdr;
            sAs[lrow + 8] = psr8; sAd[lrow + 8] = pdr8;
        }
        __syncthreads();
        if (lc == 0 && wn == 1) {
            int lrow = wm * 32 + mt * 16 + lr;
            int gr = row0 + lrow;
            if (gr < M) {
                as_out[gr] = sAs[lrow] + psr;
                ad_out[gr] = sAd[lrow] + pdr;
            }
            if (gr + 8 < M) {
                as_out[gr + 8] = sAs[lrow + 8] + psr8;
                ad_out[gr + 8] = sAd[lrow + 8] + pdr8;
            }
        }
        __syncthreads();
    }
}

// ---------------- layer-1 aggregation: shuffle-free, 2x unrolled -----------------
__global__ void agg1_kernel(const float* __restrict__ b1) {
    int w = (blockIdx.x * blockDim.x + threadIdx.x) >> 5;
    int lane = threadIdx.x & 31;
    if (w >= NN) return;
    int dst = w;
    int beg = g_off[dst], end = g_off[dst + 1];
    int hh = lane >> 1;

    float adh = __ldg(&g_ad1[(size_t)dst * HEADS + hh]);
    float exs = __expf(lrelu(__ldg(&g_as1[(size_t)dst * HEADS + hh]) + adh));
    float denom = exs;

    float acc[8];
    {
        float4 raw = __ldg((const float4*)&g_h1h[(size_t)dst * F2 + lane * 8]);
        const __half2* hp = (const __half2*)&raw;
#pragma unroll
        for (int j = 0; j < 4; j++) {
            float2 v = __half22float2(hp[j]);
            acc[j * 2 + 0] = v.x * exs;
            acc[j * 2 + 1] = v.y * exs;
        }
    }

    int i = beg;
    for (; i + 2 <= end; i += 2) {
        int s0 = g_esrc[i], s1 = g_esrc[i + 1];
        float l0 = __ldg(&g_as1[(size_t)s0 * HEADS + hh]);
        float l1 = __ldg(&g_as1[(size_t)s1 * HEADS + hh]);
        float4 r0 = __ldg((const float4*)&g_h1h[(size_t)s0 * F2 + lane * 8]);
        float4 r1 = __ldg((const float4*)&g_h1h[(size_t)s1 * F2 + lane * 8]);
        float e0 = __expf(lrelu(l0 + adh));
        float e1 = __expf(lrelu(l1 + adh));
        denom += e0 + e1;
        const __half2 *p0 = (const __half2*)&r0, *p1 = (const __half2*)&r1;
#pragma unroll
        for (int j = 0; j < 4; j++) {
            float2 v0 = __half22float2(p0[j]);
            float2 v1 = __half22float2(p1[j]);
            acc[j * 2 + 0] += v0.x * e0 + v1.x * e1;
            acc[j * 2 + 1] += v0.y * e0 + v1.y * e1;
        }
    }
    if (i < end) {
        int s = g_esrc[i];
        float ex = __expf(lrelu(__ldg(&g_as1[(size_t)s * HEADS + hh]) + adh));
        denom += ex;
        float4 raw = __ldg((const float4*)&g_h1h[(size_t)s * F2 + lane * 8]);
        const __half2* hp = (const __half2*)&raw;
#pragma unroll
        for (int j = 0; j < 4; j++) {
            float2 v = __half22float2(hp[j]);
            acc[j * 2 + 0] += v.x * ex;
            acc[j * 2 + 1] += v.y * ex;
        }
    }

    float inv = 1.0f / (denom + EPSV);
    int ch0 = lane * 8;
    __half2 o[4];
#pragma unroll
    for (int j = 0; j < 4; j++)
        o[j] = __floats2half2_rn(acc[j * 2 + 0] * inv + b1[ch0 + j * 2 + 0],
                                 acc[j * 2 + 1] * inv + b1[ch0 + j * 2 + 1]);
    *(uint2*)&g_out1h[(size_t)dst * F2 + ch0] = *(uint2*)&o[0];
    *(uint2*)&g_out1h[(size_t)dst * F2 + ch0 + 4] = *(uint2*)&o[2];
}

// ---------------- layer-2 aggregation + sigmoid (2x unrolled) --------------------
__global__ void agg2_kernel(const float* __restrict__ b2, float* __restrict__ out) {
    int w = (blockIdx.x * blockDim.x + threadIdx.x) >> 5;
    int lane = threadIdx.x & 31;
    if (w >= NN) return;
    int dst = w;
    int beg = g_off[dst], end = g_off[dst + 1];
    float adw = g_ad2[dst];
    float exs = __expf(lrelu(g_as2[dst] + adw));
    float denom = exs;
    float2 v0i = __half22float2(__ldg((const __half2*)&g_h2h[(size_t)dst * OUTC + lane * 2]));
    float2 acc = make_float2(v0i.x * exs, v0i.y * exs);

    int i = beg;
    for (; i + 2 <= end; i += 2) {
        int s0 = g_esrc[i], s1 = g_esrc[i + 1];
        float l0 = __ldg(&g_as2[s0]);
        float l1 = __ldg(&g_as2[s1]);
        float2 v0 = __half22float2(__ldg((const __half2*)&g_h2h[(size_t)s0 * OUTC + lane * 2]));
        float2 v1 = __half22float2(__ldg((const __half2*)&g_h2h[(size_t)s1 * OUTC + lane * 2]));
        float e0 = __expf(lrelu(l0 + adw));
        float e1 = __expf(lrelu(l1 + adw));
        denom += e0 + e1;
        acc.x += v0.x * e0 + v1.x * e1;
        acc.y += v0.y * e0 + v1.y * e1;
    }
    if (i < end) {
        int s = g_esrc[i];
        float ex = __expf(lrelu(__ldg(&g_as2[s]) + adw));
        denom += ex;
        float2 sv = __half22float2(__ldg((const __half2*)&g_h2h[(size_t)s * OUTC + lane * 2]));
        acc.x += sv.x * ex; acc.y += sv.y * ex;
    }
    float inv = 1.0f / (denom + EPSV);
    float x0 = acc.x * inv + b2[lane * 2 + 0];
    float x1 = acc.y * inv + b2[lane * 2 + 1];
    float2 o = make_float2(1.0f / (1.0f + __expf(-x0)), 1.0f / (1.0f + __expf(-x1)));
    *(float2*)(out + (size_t)dst * OUTC + lane * 2) = o;
}

// ---------------- launcher -------------------------------------------------------
extern "C" void kernel_launch(void* const* d_in, const int* in_sizes, int n_in,
                              void* d_out, int out_size) {
    const float* x      = (const float*)d_in[0];
    const void*  ei     = d_in[1];
    const float* W1     = (const float*)d_in[2];
    const float* a_src1 = (const float*)d_in[3];
    const float* a_dst1 = (const float*)d_in[4];
    const float* b1     = (const float*)d_in[5];
    const float* W2     = (const float*)d_in[6];
    const float* a_src2 = (const float*)d_in[7];
    const float* a_dst2 = (const float*)d_in[8];
    const float* b2     = (const float*)d_in[9];
    float* out = (float*)d_out;

    __half *xh, *w1t, *w2t, *h1, *o1, *h2;
    float *as1, *ad1, *as2, *ad2;
    cudaGetSymbolAddress((void**)&xh, g_xh);
    cudaGetSymbolAddress((void**)&w1t, g_w1t);
    cudaGetSymbolAddress((void**)&w2t, g_w2t);
    cudaGetSymbolAddress((void**)&h1, g_h1h);
    cudaGetSymbolAddress((void**)&o1, g_out1h);
    cudaGetSymbolAddress((void**)&h2, g_h2h);
    cudaGetSymbolAddress((void**)&as1, g_as1);
    cudaGetSymbolAddress((void**)&ad1, g_ad1);
    cudaGetSymbolAddress((void**)&as2, g_as2);
    cudaGetSymbolAddress((void**)&ad2, g_ad2);

    const int SMEM1 = (128 + 64) * 136 * 2;             // 52224
    const int SMEM2 = (2 * 128 * 72 + 64 * 264) * 2;    // 70656

    static cudaStream_t s_side = 0;
    static cudaEvent_t evF = 0, evJ = 0;
    if (!s_side) {
        cudaStreamCreateWithFlags(&s_side, cudaStreamNonBlocking);
        cudaEventCreateWithFlags(&evF, cudaEventDisableTiming);
        cudaEventCreateWithFlags(&evJ, cudaEventDisableTiming);
        cudaFuncSetAttribute(gemm1_ca, cudaFuncAttributeMaxDynamicSharedMemorySize, SMEM1);
        cudaFuncSetAttribute(gemm2_ca, cudaFuncAttributeMaxDynamicSharedMemorySize, SMEM2);
    }

    // main stream: converts (submit #1, #2)
    xconv_kernel<<<(NN * F1 / 4 + 255) / 256, 256>>>(x);
    wt_kernel<<<(F1 * F2 + F2 * OUTC + 255) / 256, 256>>>(W1, W2);

    // fork: CSR build on side stream
    cudaEventRecord(evF, 0);
    cudaStreamWaitEvent(s_side, evF, 0);
    hist_kernel<<<(EE / 8 + 255) / 256, 256, 0, s_side>>>(ei);        // #3

    // main stream: GEMM1 (#4 - ncu window)
    {
        dim3 grid(F2 / 64, (NN + 127) / 128);
        gemm1_ca<<<grid, 256, SMEM1>>>(xh, w1t, h1, a_src1, a_dst1, as1, ad1, NN);
    }

    scanA_kernel<<<SCAN_BLK, 1024, 0, s_side>>>();                    // #5
    scanC_kernel<<<SCAN_BLK, 1024, 0, s_side>>>();                    // #6
    scatter_kernel<<<(EE / 8 + 255) / 256, 256, 0, s_side>>>(ei);     // #7
    cudaEventRecord(evJ, s_side);

    cudaStreamWaitEvent(0, evJ, 0);

    agg1_kernel<<<(NN * 32 + 255) / 256, 256>>>(b1);
    gemm2_ca<<<(NN + 127) / 128, 256, SMEM2>>>(o1, w2t, h2, a_src2, a_dst2, as2, ad2, NN);
    agg2_kernel<<<(NN * 32 + 255) / 256, 256>>>(b2, out);
}

// round 17
// speedup vs baseline: 1.0118x; 1.0118x over previous
#include <cuda_runtime.h>
#include <cuda_fp16.h>
#include <cuda_bf16.h>

#define NN 50000
#define EE 800000
#define F1 128
#define F2 256   // HEADS*HID
#define HEADS 16
#define HID 16
#define OUTC 64
#define NEG_SLOPE 0.2f
#define EPSV 1e-16f
#define SCAN_BLK 49

// ---------------- scratch (zero-initialized at module load) --------------------
__device__ __half g_xh[(size_t)NN * F1];     // x in half
__device__ __half g_w1t[F2 * F1];            // W1^T [n][k], swizzled, half
__device__ __half g_w2t[OUTC * F2];          // W2^T [n][k], swizzled, half
__device__ __half g_h1h[(size_t)NN * F2];
__device__ __half g_out1h[(size_t)NN * F2];
__device__ __half g_h2h[(size_t)NN * OUTC];
__device__ float  g_as1[(size_t)NN * HEADS];
__device__ float  g_ad1[(size_t)NN * HEADS];
__device__ float  g_as2[NN];
__device__ float  g_ad2[NN];
__device__ int    g_cnt[NN];
__device__ int    g_off[NN + 1];
__device__ int    g_esrc[EE];
__device__ int    g_rank[EE];
__device__ int    g_bsum[64];

// ---------------- helpers -----------------------------------------------------
__device__ __forceinline__ float lrelu(float e) { return e > 0.f ? e : NEG_SLOPE * e; }

__device__ __forceinline__ int is_i32(const void* ei) {
    const int* w = (const int*)ei;
    return (w[1] | w[3] | w[5] | w[7]) != 0;
}

__device__ __forceinline__ void hmma16816(float* d, const unsigned* a, const unsigned* b) {
    asm volatile(
        "mma.sync.aligned.m16n8k16.row.col.f32.f16.f16.f32 "
        "{%0,%1,%2,%3}, {%4,%5,%6,%7}, {%8,%9}, {%0,%1,%2,%3};"
        : "+f"(d[0]), "+f"(d[1]), "+f"(d[2]), "+f"(d[3])
        : "r"(a[0]), "r"(a[1]), "r"(a[2]), "r"(a[3]), "r"(b[0]), "r"(b[1]));
}

__device__ __forceinline__ void ldsm_x4(unsigned& r0, unsigned& r1, unsigned& r2,
                                        unsigned& r3, unsigned addr) {
    asm volatile("ldmatrix.sync.aligned.m8n8.x4.shared.b16 {%0,%1,%2,%3}, [%4];"
                 : "=r"(r0), "=r"(r1), "=r"(r2), "=r"(r3) : "r"(addr));
}

__device__ __forceinline__ void cp16(unsigned dst, const void* src, int sz) {
    asm volatile("cp.async.cg.shared.global [%0], [%1], 16, %2;"
                 :: "r"(dst), "l"(src), "r"(sz));
}

// ---------------- converts --------------------------------------------------------
__global__ void xconv_kernel(const float* __restrict__ x) {
    int i = blockIdx.x * blockDim.x + threadIdx.x;
    if (i >= NN * F1 / 4) return;
    float4 v = ((const float4*)x)[i];
    __half2 p0 = __floats2half2_rn(v.x, v.y);
    __half2 p1 = __floats2half2_rn(v.z, v.w);
    uint2 u; u.x = *(unsigned*)&p0; u.y = *(unsigned*)&p1;
    ((uint2*)g_xh)[i] = u;
}

__global__ void wt_kernel(const float* __restrict__ W1, const float* __restrict__ W2) {
    int idx = blockIdx.x * blockDim.x + threadIdx.x;
    if (idx < F1 * F2) {                      // W1: [k=128][n=256]
        int k = idx >> 8, n = idx & 255;
        int sw = ((n >> 3) & 7) << 3;
        int ks = (k & 64) | ((k & 63) ^ sw);
        g_w1t[n * F1 + ks] = __float2half_rn(W1[idx]);
    } else if (idx < F1 * F2 + F2 * OUTC) {   // W2: [k=256][n=64]
        int j = idx - F1 * F2;
        int k = j >> 6, n = j & 63;
        int sw = ((n >> 3) & 7) << 3;
        int ks = (k & 192) | ((k & 63) ^ sw);
        g_w2t[n * F2 + ks] = __float2half_rn(W2[j]);
    }
}

// ---------------- hist (+rank), 8 edges/thread --------------------------------------
__global__ void hist_kernel(const void* ei) {
    int i = (blockIdx.x * blockDim.x + threadIdx.x) * 8;
    if (i >= EE) return;
    int d[8];
    if (is_i32(ei)) {
        const int* p = (const int*)ei;
        int4 a = *(const int4*)&p[EE + i];
        int4 b = *(const int4*)&p[EE + i + 4];
        d[0] = a.x; d[1] = a.y; d[2] = a.z; d[3] = a.w;
        d[4] = b.x; d[5] = b.y; d[6] = b.z; d[7] = b.w;
    } else {
        const long long* p = (const long long*)ei;
#pragma unroll
        for (int j = 0; j < 4; j++) {
            longlong2 v = *(const longlong2*)&p[EE + i + j * 2];
            d[j * 2] = (int)v.x; d[j * 2 + 1] = (int)v.y;
        }
    }
    int r[8];
#pragma unroll
    for (int j = 0; j < 8; j++) r[j] = atomicAdd(&g_cnt[d[j]], 1);
#pragma unroll
    for (int j = 0; j < 8; j++) g_rank[i + j] = r[j];
}

// ---------------- two-phase scan ------------------------------------------------------
__global__ void scanA_kernel() {
    __shared__ int wsum[32];
    int i = blockIdx.x * 1024 + threadIdx.x;
    int lane = threadIdx.x & 31, wid = threadIdx.x >> 5;
    int x = (i < NN) ? g_cnt[i] : 0;
    int incl = x;
#pragma unroll
    for (int d = 1; d < 32; d <<= 1) {
        int t = __shfl_up_sync(0xffffffffu, incl, d);
        if (lane >= d) incl += t;
    }
    if (lane == 31) wsum[wid] = incl;
    __syncthreads();
    if (wid == 0) {
        int y = wsum[lane];
#pragma unroll
        for (int d = 1; d < 32; d <<= 1) {
            int t = __shfl_up_sync(0xffffffffu, y, d);
            if (lane >= d) y += t;
        }
        wsum[lane] = y;
    }
    __syncthreads();
    if (wid > 0) incl += wsum[wid - 1];
    if (i < NN) g_off[i + 1] = incl;
    if (threadIdx.x == 1023) g_bsum[blockIdx.x] = incl;
}

__global__ void scanC_kernel() {
    __shared__ int sb[64];
    __shared__ int base_s;
    int t = threadIdx.x;
    if (t < 64) sb[t] = (t < SCAN_BLK) ? g_bsum[t] : 0;
    __syncthreads();
    if (t == 0) {
        int s = 0;
        int n = blockIdx.x;
        for (int j = 0; j < n; j++) s += sb[j];
        base_s = s;
    }
    __syncthreads();
    int i = blockIdx.x * 1024 + t;
    if (i < NN) {
        g_off[i + 1] += base_s;
        g_cnt[i] = 0;
    }
    if (i == 0) g_off[0] = 0;
}

// ---------------- scatter without atomics, 8 edges/thread ----------------------------
__global__ void scatter_kernel(const void* ei) {
    int i = (blockIdx.x * blockDim.x + threadIdx.x) * 8;
    if (i >= EE) return;
    int s[8], d[8];
    if (is_i32(ei)) {
        const int* p = (const int*)ei;
        int4 sa = *(const int4*)&p[i];
        int4 sbv = *(const int4*)&p[i + 4];
        int4 da = *(const int4*)&p[EE + i];
        int4 db = *(const int4*)&p[EE + i + 4];
        s[0] = sa.x; s[1] = sa.y; s[2] = sa.z; s[3] = sa.w;
        s[4] = sbv.x; s[5] = sbv.y; s[6] = sbv.z; s[7] = sbv.w;
        d[0] = da.x; d[1] = da.y; d[2] = da.z; d[3] = da.w;
        d[4] = db.x; d[5] = db.y; d[6] = db.z; d[7] = db.w;
    } else {
        const long long* p = (const long long*)ei;
#pragma unroll
        for (int j = 0; j < 4; j++) {
            longlong2 sv = *(const longlong2*)&p[i + j * 2];
            longlong2 dv = *(const longlong2*)&p[EE + i + j * 2];
            s[j * 2] = (int)sv.x; s[j * 2 + 1] = (int)sv.y;
            d[j * 2] = (int)dv.x; d[j * 2 + 1] = (int)dv.y;
        }
    }
    int4 ra = *(const int4*)&g_rank[i];
    int4 rb = *(const int4*)&g_rank[i + 4];
    int r[8] = {ra.x, ra.y, ra.z, ra.w, rb.x, rb.y, rb.z, rb.w};
    int o[8];
#pragma unroll
    for (int j = 0; j < 8; j++) o[j] = g_off[d[j]];
#pragma unroll
    for (int j = 0; j < 8; j++) g_esrc[o[j] + r[j]] = s[j];
}

// ---------------- GEMM1: cp.async full-K single stage, fused 16-head alpha -------
__global__ void gemm1_ca(const __half* __restrict__ Axh, const __half* __restrict__ w1t,
                         __half* __restrict__ C,
                         const float* __restrict__ avs, const float* __restrict__ avd,
                         float* __restrict__ as_out, float* __restrict__ ad_out, int M) {
    extern __shared__ __half sm[];
    __half* As = sm;                 // [128][136]
    __half* Bs = sm + 128 * 136;     // [64][136]

    int tid = threadIdx.x;
    int wid = tid >> 5, lane = tid & 31;
    int wm = wid & 3, wn = wid >> 2;
    int row0 = blockIdx.y * 128, col0 = blockIdx.x * 64;
    int lr = lane >> 2, lc = lane & 3;

    unsigned as_base = (unsigned)__cvta_generic_to_shared(As);
    unsigned bs_base = (unsigned)__cvta_generic_to_shared(Bs);

    int g8 = lane >> 3, ri = lane & 7;
    int gA_row = ((g8 & 1) << 3) + ri;
    int gA_col = (g8 >> 1) << 3;
    int gB_nhi = (g8 >> 1) << 3;
    int gB_k   = (g8 & 1) << 3;

#pragma unroll
    for (int l = 0; l < 8; l++) {
        int idx = tid + l * 256;
        int r = idx >> 4, c = idx & 15;
        int gr = row0 + r;
        unsigned dst = as_base + (unsigned)((r * 136 + c * 8) * 2);
        const __half* src = &Axh[(size_t)gr * F1 + c * 8];
        cp16(dst, src, (gr < M) ? 16 : 0);
    }
#pragma unroll
    for (int l = 0; l < 4; l++) {
        int idx = tid + l * 256;
        int r = idx >> 4, c = idx & 15;
        unsigned dst = bs_base + (unsigned)((r * 136 + c * 8) * 2);
        const __half* src = &w1t[(size_t)(col0 + r) * F1 + c * 8];
        cp16(dst, src, 16);
    }
    asm volatile("cp.async.commit_group;");
    asm volatile("cp.async.wait_group 0;");
    __syncthreads();

    float d[2][4][4];
#pragma unroll
    for (int a = 0; a < 2; a++)
#pragma unroll
        for (int b = 0; b < 4; b++)
#pragma unroll
            for (int c = 0; c < 4; c++) d[a][b][c] = 0.f;

#pragma unroll
    for (int kk = 0; kk < 8; kk++) {
        int kb = kk * 16;
        unsigned afr[2][4], bfr[4][2];
#pragma unroll
        for (int mt = 0; mt < 2; mt++) {
            int r = wm * 32 + mt * 16 + gA_row;
            unsigned addr = as_base + (unsigned)((r * 136 + kb + gA_col) * 2);
            ldsm_x4(afr[mt][0], afr[mt][1], afr[mt][2], afr[mt][3], addr);
        }
#pragma unroll
        for (int ntp = 0; ntp < 2; ntp++) {
            int nrow = wn * 32 + ntp * 16 + gB_nhi + ri;
            int sw = ((nrow >> 3) & 7) << 3;
            int kidx = (kb + gB_k) ^ sw;
            unsigned addr = bs_base + (unsigned)((nrow * 136 + kidx) * 2);
            ldsm_x4(bfr[ntp * 2][0], bfr[ntp * 2][1],
                    bfr[ntp * 2 + 1][0], bfr[ntp * 2 + 1][1], addr);
        }
#pragma unroll
        for (int mt = 0; mt < 2; mt++)
#pragma unroll
            for (int nt = 0; nt < 4; nt++)
                hmma16816(d[mt][nt], afr[mt], bfr[nt]);
    }

#pragma unroll
    for (int mt = 0; mt < 2; mt++) {
        int gr0 = row0 + wm * 32 + mt * 16 + lr;
#pragma unroll
        for (int nt = 0; nt < 4; nt++) {
            int gc = col0 + wn * 32 + nt * 8 + lc * 2;
            if (gr0 < M) {
                __half2 p = __floats2half2_rn(d[mt][nt][0], d[mt][nt][1]);
                *(unsigned*)&C[(size_t)gr0 * F2 + gc] = *(unsigned*)&p;
            }
            if (gr0 + 8 < M) {
                __half2 p = __floats2half2_rn(d[mt][nt][2], d[mt][nt][3]);
                *(unsigned*)&C[(size_t)(gr0 + 8) * F2 + gc] = *(unsigned*)&p;
            }
        }
    }

#pragma unroll
    for (int mt = 0; mt < 2; mt++) {
#pragma unroll
        for (int hp = 0; hp < 2; hp++) {
            int h = blockIdx.x * 4 + wn * 2 + hp;
            float psr = 0.f, pdr = 0.f, psr8 = 0.f, pdr8 = 0.f;
#pragma unroll
            for (int half_t = 0; half_t < 2; half_t++) {
                int nt = hp * 2 + half_t;
                int cl = half_t * 8 + lc * 2;
                float w0s = avs[h * HID + cl], w1s = avs[h * HID + cl + 1];
                float w0d = avd[h * HID + cl], w1d = avd[h * HID + cl + 1];
                psr  += d[mt][nt][0] * w0s + d[mt][nt][1] * w1s;
                pdr  += d[mt][nt][0] * w0d + d[mt][nt][1] * w1d;
                psr8 += d[mt][nt][2] * w0s + d[mt][nt][3] * w1s;
                pdr8 += d[mt][nt][2] * w0d + d[mt][nt][3] * w1d;
            }
#pragma unroll
            for (int dx = 1; dx <= 2; dx <<= 1) {
                psr  += __shfl_xor_sync(0xffffffffu, psr, dx);
                pdr  += __shfl_xor_sync(0xffffffffu, pdr, dx);
                psr8 += __shfl_xor_sync(0xffffffffu, psr8, dx);
                pdr8 += __shfl_xor_sync(0xffffffffu, pdr8, dx);
            }
            if (lc == 0) {
                int gr = row0 + wm * 32 + mt * 16 + lr;
                if (gr < M) {
                    as_out[(size_t)gr * HEADS + h] = psr;
                    ad_out[(size_t)gr * HEADS + h] = pdr;
                }
                if (gr + 8 < M) {
                    as_out[(size_t)(gr + 8) * HEADS + h] = psr8;
                    ad_out[(size_t)(gr + 8) * HEADS + h] = pdr8;
                }
            }
        }
    }
}

// ---------------- GEMM2: cp.async pipelined (B resident, A double-buffered) ------
__global__ void gemm2_ca(const __half* __restrict__ A, const __half* __restrict__ w2t,
                         __half* __restrict__ C,
                         const float* __restrict__ avs, const float* __restrict__ avd,
                         float* __restrict__ as_out, float* __restrict__ ad_out, int M) {
    extern __shared__ __half sm[];
    __half* As = sm;
    __half* Bs = sm + 2 * 128 * 72;
    __shared__ float sAs[128], sAd[128];

    int tid = threadIdx.x;
    int wid = tid >> 5, lane = tid & 31;
    int wm = wid & 3, wn = wid >> 2;
    int row0 = blockIdx.x * 128;
    int lr = lane >> 2, lc = lane & 3;

    unsigned as_base = (unsigned)__cvta_generic_to_shared(As);
    unsigned bs_base = (unsigned)__cvta_generic_to_shared(Bs);

    int g8 = lane >> 3, ri = lane & 7;
    int gA_row = ((g8 & 1) << 3) + ri;
    int gA_col = (g8 >> 1) << 3;
    int gB_nhi = (g8 >> 1) << 3;
    int gB_k   = (g8 & 1) << 3;

#pragma unroll
    for (int l = 0; l < 8; l++) {
        int idx = tid + l * 256;
        int r = idx >> 5, c = idx & 31;
        unsigned dst = bs_base + (unsigned)((r * 264 + c * 8) * 2);
        cp16(dst, &w2t[(size_t)r * F2 + c * 8], 16);
    }
#pragma unroll
    for (int l = 0; l < 4; l++) {
        int idx = tid + l * 256;
        int r = idx >> 3, c = idx & 7;
        int gr = row0 + r;
        unsigned dst = as_base + (unsigned)((r * 72 + c * 8) * 2);
        cp16(dst, &A[(size_t)gr * F2 + 0 + c * 8], (gr < M) ? 16 : 0);
    }
    asm volatile("cp.async.commit_group;");
#pragma unroll
    for (int l = 0; l < 4; l++) {
        int idx = tid + l * 256;
        int r = idx >> 3, c = idx & 7;
        int gr = row0 + r;
        unsigned dst = as_base + (unsigned)((128 * 72 + r * 72 + c * 8) * 2);
        cp16(dst, &A[(size_t)gr * F2 + 64 + c * 8], (gr < M) ? 16 : 0);
    }
    asm volatile("cp.async.commit_group;");

    float d[2][4][4];
#pragma unroll
    for (int a = 0; a < 2; a++)
#pragma unroll
        for (int b = 0; b < 4; b++)
#pragma unroll
            for (int c = 0; c < 4; c++) d[a][b][c] = 0.f;

#pragma unroll
    for (int kc = 0; kc < 4; kc++) {
        if (kc < 3) asm volatile("cp.async.wait_group 1;");
        else        asm volatile("cp.async.wait_group 0;");
        __syncthreads();

        unsigned stage = as_base + (unsigned)((kc & 1) * 128 * 72 * 2);
#pragma unroll
        for (int kk = 0; kk < 4; kk++) {
            int kbl = kk * 16;
            int kbg = kc * 64 + kbl;
            unsigned afr[2][4], bfr[4][2];
#pragma unroll
            for (int mt = 0; mt < 2; mt++) {
                int r = wm * 32 + mt * 16 + gA_row;
                unsigned addr = stage + (unsigned)((r * 72 + kbl + gA_col) * 2);
                ldsm_x4(afr[mt][0], afr[mt][1], afr[mt][2], afr[mt][3], addr);
            }
#pragma unroll
            for (int ntp = 0; ntp < 2; ntp++) {
                int nrow = wn * 32 + ntp * 16 + gB_nhi + ri;
                int sw = ((nrow >> 3) & 7) << 3;
                int kidx = (kbg + gB_k) ^ sw;
                unsigned addr = bs_base + (unsigned)((nrow * 264 + kidx) * 2);
                ldsm_x4(bfr[ntp * 2][0], bfr[ntp * 2][1],
                        bfr[ntp * 2 + 1][0], bfr[ntp * 2 + 1][1], addr);
            }
#pragma unroll
            for (int mt = 0; mt < 2; mt++)
#pragma unroll
                for (int nt = 0; nt < 4; nt++)
                    hmma16816(d[mt][nt], afr[mt], bfr[nt]);
        }
        __syncthreads();

        if (kc + 2 < 4) {
#pragma unroll
            for (int l = 0; l < 4; l++) {
                int idx = tid + l * 256;
                int r = idx >> 3, c = idx & 7;
                int gr = row0 + r;
                unsigned dst = as_base + (unsigned)(((kc & 1) * 128 * 72 + r * 72 + c * 8) * 2);
                cp16(dst, &A[(size_t)gr * F2 + (kc + 2) * 64 + c * 8], (gr < M) ? 16 : 0);
            }
            asm volatile("cp.async.commit_group;");
        }
    }

#pragma unroll
    for (int mt = 0; mt < 2; mt++) {
        int gr0 = row0 + wm * 32 + mt * 16 + lr;
#pragma unroll
        for (int nt = 0; nt < 4; nt++) {
            int gc = wn * 32 + nt * 8 + lc * 2;
            if (gr0 < M) {
                __half2 p = __floats2half2_rn(d[mt][nt][0], d[mt][nt][1]);
                *(unsigned*)&C[(size_t)gr0 * OUTC + gc] = *(unsigned*)&p;
            }
            if (gr0 + 8 < M) {
                __half2 p = __floats2half2_rn(d[mt][nt][2], d[mt][nt][3]);
                *(unsigned*)&C[(size_t)(gr0 + 8) * OUTC + gc] = *(unsigned*)&p;
            }
        }
    }

#pragma unroll
    for (int mt = 0; mt < 2; mt++) {
        float psr = 0.f, pdr = 0.f, psr8 = 0.f, pdr8 = 0.f;
#pragma unroll
        for (int nt = 0; nt < 4; nt++) {
            int cl = wn * 32 + nt * 8 + lc * 2;
            float w0s = avs[cl], w1s = avs[cl + 1];
            float w0d = avd[cl], w1d = avd[cl + 1];
            psr  += d[mt][nt][0] * w0s + d[mt][nt][1] * w1s;
            pdr  += d[mt][nt][0] * w0d + d[mt][nt][1] * w1d;
            psr8 += d[mt][nt][2] * w0s + d[mt][nt][3] * w1s;
            pdr8 += d[mt][nt][2] * w0d + d[mt][nt][3] * w1d;
        }
#pragma unroll
        for (int dx = 1; dx <= 2; dx <<= 1) {
            psr  += __shfl_xor_sync(0xffffffffu, psr, dx);
            pdr  += __shfl_xor_sync(0xffffffffu, pdr, dx);
            psr8 += __shfl_xor_sync(0xffffffffu, psr8, dx);
            pdr8 += __shfl_xor_sync(0xffffffffu, pdr8, dx);
        }
        if (lc == 0 && wn == 0) {
            int lrow = wm * 32 + mt * 16 + lr;
            sAs[lrow] = psr;  sAd[lrow] = pdr;
            sAs[lrow + 8] = psr8; sAd[lrow + 8] = pdr8;
        }
        __syncthreads();
        if (lc == 0 && wn == 1) {
            int lrow = wm * 32 + mt * 16 + lr;
            int gr = row0 + lrow;
            if (gr < M) {
                as_out[gr] = sAs[lrow] + psr;
                ad_out[gr] = sAd[lrow] + pdr;
            }
            if (gr + 8 < M) {
                as_out[gr + 8] = sAs[lrow + 8] + psr8;
                ad_out[gr + 8] = sAd[lrow + 8] + pdr8;
            }
        }
        __syncthreads();
    }
}

// ---------------- layer-1 aggregation: shuffle-free, 2x unrolled -----------------
__global__ void agg1_kernel(const float* __restrict__ b1) {
    int w = (blockIdx.x * blockDim.x + threadIdx.x) >> 5;
    int lane = threadIdx.x & 31;
    if (w >= NN) return;
    int dst = w;
    int beg = g_off[dst], end = g_off[dst + 1];
    int hh = lane >> 1;

    float adh = __ldg(&g_ad1[(size_t)dst * HEADS + hh]);
    float exs = __expf(lrelu(__ldg(&g_as1[(size_t)dst * HEADS + hh]) + adh));
    float denom = exs;

    float acc[8];
    {
        float4 raw = __ldg((const float4*)&g_h1h[(size_t)dst * F2 + lane * 8]);
        const __half2* hp = (const __half2*)&raw;
#pragma unroll
        for (int j = 0; j < 4; j++) {
            float2 v = __half22float2(hp[j]);
            acc[j * 2 + 0] = v.x * exs;
            acc[j * 2 + 1] = v.y * exs;
        }
    }

    int i = beg;
    for (; i + 2 <= end; i += 2) {
        int s0 = g_esrc[i], s1 = g_esrc[i + 1];
        float l0 = __ldg(&g_as1[(size_t)s0 * HEADS + hh]);
        float l1 = __ldg(&g_as1[(size_t)s1 * HEADS + hh]);
        float4 r0 = __ldg((const float4*)&g_h1h[(size_t)s0 * F2 + lane * 8]);
        float4 r1 = __ldg((const float4*)&g_h1h[(size_t)s1 * F2 + lane * 8]);
        float e0 = __expf(lrelu(l0 + adh));
        float e1 = __expf(lrelu(l1 + adh));
        denom += e0 + e1;
        const __half2 *p0 = (const __half2*)&r0, *p1 = (const __half2*)&r1;
#pragma unroll
        for (int j = 0; j < 4; j++) {
            float2 v0 = __half22float2(p0[j]);
            float2 v1 = __half22float2(p1[j]);
            acc[j * 2 + 0] += v0.x * e0 + v1.x * e1;
            acc[j * 2 + 1] += v0.y * e0 + v1.y * e1;
        }
    }
    if (i < end) {
        int s = g_esrc[i];
        float ex = __expf(lrelu(__ldg(&g_as1[(size_t)s * HEADS + hh]) + adh));
        denom += ex;
        float4 raw = __ldg((const float4*)&g_h1h[(size_t)s * F2 + lane * 8]);
        const __half2* hp = (const __half2*)&raw;
#pragma unroll
        for (int j = 0; j < 4; j++) {
            float2 v = __half22float2(hp[j]);
            acc[j * 2 + 0] += v.x * ex;
            acc[j * 2 + 1] += v.y * ex;
        }
    }

    float inv = 1.0f / (denom + EPSV);
    int ch0 = lane * 8;
    __half2 o[4];
#pragma unroll
    for (int j = 0; j < 4; j++)
        o[j] = __floats2half2_rn(acc[j * 2 + 0] * inv + b1[ch0 + j * 2 + 0],
                                 acc[j * 2 + 1] * inv + b1[ch0 + j * 2 + 1]);
    *(uint2*)&g_out1h[(size_t)dst * F2 + ch0] = *(uint2*)&o[0];
    *(uint2*)&g_out1h[(size_t)dst * F2 + ch0 + 4] = *(uint2*)&o[2];
}

// ---------------- layer-2 aggregation: half-warp per edge, sigmoid ----------------
__global__ void agg2_kernel(const float* __restrict__ b2, float* __restrict__ out) {
    int w = (blockIdx.x * blockDim.x + threadIdx.x) >> 5;
    int lane = threadIdx.x & 31;
    if (w >= NN) return;
    int dst = w;
    int beg = g_off[dst], end = g_off[dst + 1];
    int hf = lane >> 4;      // which half-warp
    int li = lane & 15;      // lane within half: channels li*4..li*4+3
    float adw = g_ad2[dst];

    float denom = 0.f;
    float acc[4] = {0.f, 0.f, 0.f, 0.f};

    if (hf == 0) {
        float exs = __expf(lrelu(__ldg(&g_as2[dst]) + adw));
        denom = exs;
        uint2 raw = __ldg((const uint2*)&g_h2h[(size_t)dst * OUTC + li * 4]);
        const __half2* hp = (const __half2*)&raw;
        float2 v0 = __half22float2(hp[0]);
        float2 v1 = __half22float2(hp[1]);
        acc[0] = v0.x * exs; acc[1] = v0.y * exs;
        acc[2] = v1.x * exs; acc[3] = v1.y * exs;
    }

    int i = beg + hf;
    // 2x unrolled over this half's edges (stride 2 within half => stride 4 pairs)
    for (; i + 2 < end; i += 4) {
        int s0 = g_esrc[i], s1 = g_esrc[i + 2];
        float l0 = __ldg(&g_as2[s0]);
        float l1 = __ldg(&g_as2[s1]);
        uint2 r0 = __ldg((const uint2*)&g_h2h[(size_t)s0 * OUTC + li * 4]);
        uint2 r1 = __ldg((const uint2*)&g_h2h[(size_t)s1 * OUTC + li * 4]);
        float e0 = __expf(lrelu(l0 + adw));
        float e1 = __expf(lrelu(l1 + adw));
        denom += e0 + e1;
        const __half2 *p0 = (const __half2*)&r0, *p1 = (const __half2*)&r1;
        float2 a0 = __half22float2(p0[0]), a1 = __half22float2(p0[1]);
        float2 c0 = __half22float2(p1[0]), c1 = __half22float2(p1[1]);
        acc[0] += a0.x * e0 + c0.x * e1;
        acc[1] += a0.y * e0 + c0.y * e1;
        acc[2] += a1.x * e0 + c1.x * e1;
        acc[3] += a1.y * e0 + c1.y * e1;
    }
    if (i < end) {
        int s = g_esrc[i];
        float ex = __expf(lrelu(__ldg(&g_as2[s]) + adw));
        denom += ex;
        uint2 raw = __ldg((const uint2*)&g_h2h[(size_t)s * OUTC + li * 4]);
        const __half2* hp = (const __half2*)&raw;
        float2 v0 = __half22float2(hp[0]);
        float2 v1 = __half22float2(hp[1]);
        acc[0] += v0.x * ex; acc[1] += v0.y * ex;
        acc[2] += v1.x * ex; acc[3] += v1.y * ex;
    }

    // combine the two halves
    denom += __shfl_xor_sync(0xffffffffu, denom, 16);
#pragma unroll
    for (int c = 0; c < 4; c++)
        acc[c] += __shfl_xor_sync(0xffffffffu, acc[c], 16);

    if (hf == 0) {
        float inv = 1.0f / (denom + EPSV);
        float4 o;
        float x0 = acc[0] * inv + b2[li * 4 + 0];
        float x1 = acc[1] * inv + b2[li * 4 + 1];
        float x2 = acc[2] * inv + b2[li * 4 + 2];
        float x3 = acc[3] * inv + b2[li * 4 + 3];
        o.x = 1.0f / (1.0f + __expf(-x0));
        o.y = 1.0f / (1.0f + __expf(-x1));
        o.z = 1.0f / (1.0f + __expf(-x2));
        o.w = 1.0f / (1.0f + __expf(-x3));
        *(float4*)&out[(size_t)dst * OUTC + li * 4] = o;
    }
}

// ---------------- launcher -------------------------------------------------------
extern "C" void kernel_launch(void* const* d_in, const int* in_sizes, int n_in,
                              void* d_out, int out_size) {
    const float* x      = (const float*)d_in[0];
    const void*  ei     = d_in[1];
    const float* W1     = (const float*)d_in[2];
    const float* a_src1 = (const float*)d_in[3];
    const float* a_dst1 = (const float*)d_in[4];
    const float* b1     = (const float*)d_in[5];
    const float* W2     = (const float*)d_in[6];
    const float* a_src2 = (const float*)d_in[7];
    const float* a_dst2 = (const float*)d_in[8];
    const float* b2     = (const float*)d_in[9];
    float* out = (float*)d_out;

    __half *xh, *w1t, *w2t, *h1, *o1, *h2;
    float *as1, *ad1, *as2, *ad2;
    cudaGetSymbolAddress((void**)&xh, g_xh);
    cudaGetSymbolAddress((void**)&w1t, g_w1t);
    cudaGetSymbolAddress((void**)&w2t, g_w2t);
    cudaGetSymbolAddress((void**)&h1, g_h1h);
    cudaGetSymbolAddress((void**)&o1, g_out1h);
    cudaGetSymbolAddress((void**)&h2, g_h2h);
    cudaGetSymbolAddress((void**)&as1, g_as1);
    cudaGetSymbolAddress((void**)&ad1, g_ad1);
    cudaGetSymbolAddress((void**)&as2, g_as2);
    cudaGetSymbolAddress((void**)&ad2, g_ad2);

    const int SMEM1 = (128 + 64) * 136 * 2;             // 52224
    const int SMEM2 = (2 * 128 * 72 + 64 * 264) * 2;    // 70656

    static cudaStream_t s_side = 0;
    static cudaEvent_t evF = 0, evJ = 0;
    if (!s_side) {
        cudaStreamCreateWithFlags(&s_side, cudaStreamNonBlocking);
        cudaEventCreateWithFlags(&evF, cudaEventDisableTiming);
        cudaEventCreateWithFlags(&evJ, cudaEventDisableTiming);
        cudaFuncSetAttribute(gemm1_ca, cudaFuncAttributeMaxDynamicSharedMemorySize, SMEM1);
        cudaFuncSetAttribute(gemm2_ca, cudaFuncAttributeMaxDynamicSharedMemorySize, SMEM2);
    }

    // main stream: converts
    xconv_kernel<<<(NN * F1 / 4 + 255) / 256, 256>>>(x);
    wt_kernel<<<(F1 * F2 + F2 * OUTC + 255) / 256, 256>>>(W1, W2);

    // fork: CSR build on side stream
    cudaEventRecord(evF, 0);
    cudaStreamWaitEvent(s_side, evF, 0);
    hist_kernel<<<(EE / 8 + 255) / 256, 256, 0, s_side>>>(ei);

    // main stream: GEMM1 (#4 - ncu window)
    {
        dim3 grid(F2 / 64, (NN + 127) / 128);
        gemm1_ca<<<grid, 256, SMEM1>>>(xh, w1t, h1, a_src1, a_dst1, as1, ad1, NN);
    }

    scanA_kernel<<<SCAN_BLK, 1024, 0, s_side>>>();
    scanC_kernel<<<SCAN_BLK, 1024, 0, s_side>>>();
    scatter_kernel<<<(EE / 8 + 255) / 256, 256, 0, s_side>>>(ei);
    cudaEventRecord(evJ, s_side);

    cudaStreamWaitEvent(0, evJ, 0);

    agg1_kernel<<<(NN * 32 + 255) / 256, 256>>>(b1);
    gemm2_ca<<<(NN + 127) / 128, 256, SMEM2>>>(o1, w2t, h2, a_src2, a_dst2, as2, ad2, NN);
    agg2_kernel<<<(NN * 32 + 255) / 256, 256>>>(b2, out);
}